// round 6
// baseline (speedup 1.0000x reference)
#include <cuda_runtime.h>
#include <cstdint>

#define MAXB 64
#define MAXP 8800
#define MAXN 64

// ---------------- scratch (device globals) ----------------
__device__ int                g_bti[MAXB * MAXP];     // best_truth_idx
__device__ int                g_pos0[MAXB * MAXP];    // iou >= 0.5 flag
__device__ int                g_ovr[MAXB * MAXP];     // override: n+1, 0 = none
__device__ float              g_lossc[MAXB * MAXP];   // loss_c (0 for pos)
__device__ unsigned long long g_key[MAXB * MAXN];     // per-GT best prior key
__device__ int                g_numpos[MAXB];
__device__ int                g_bdone[MAXB];          // match completion per batch
__device__ int                g_ldone[MAXB];          // loss completion per batch
__device__ int                g_done;                 // select completion
__device__ double             g_acc[3];               // loc, ce_pos, ce_neg

// ---------------- reductions ----------------
__device__ __forceinline__ double warpSumD(double v) {
#pragma unroll
    for (int o = 16; o; o >>= 1) v += __shfl_down_sync(0xFFFFFFFFu, v, o);
    return v;
}
__device__ __forceinline__ int warpSumI(int v) {
#pragma unroll
    for (int o = 16; o; o >>= 1) v += __shfl_down_sync(0xFFFFFFFFu, v, o);
    return v;
}
// inclusive suffix sum within warp: result(lane) = sum over lanes >= lane
__device__ __forceinline__ int warpSufI(int v) {
    int lane = threadIdx.x & 31;
#pragma unroll
    for (int o = 1; o < 32; o <<= 1) {
        int t = __shfl_down_sync(0xFFFFFFFFu, v, o);
        if (lane + o < 32) v += t;
    }
    return v;
}

__device__ int blockSumI(int v, int* sh) {
    __syncthreads();
    int lane = threadIdx.x & 31, wid = threadIdx.x >> 5;
    v = warpSumI(v);
    if (lane == 0) sh[wid] = v;
    __syncthreads();
    if (wid == 0) {
        int nw = (blockDim.x + 31) >> 5;
        int x = (lane < nw) ? sh[lane] : 0;
        x = warpSumI(x);
        if (lane == 0) sh[0] = x;
    }
    __syncthreads();
    return sh[0];
}

__device__ double blockSumD(double v, double* sh) {
    __syncthreads();
    int lane = threadIdx.x & 31, wid = threadIdx.x >> 5;
    v = warpSumD(v);
    if (lane == 0) sh[wid] = v;
    __syncthreads();
    if (wid == 0) {
        int nw = (blockDim.x + 31) >> 5;
        double x = (lane < nw) ? sh[lane] : 0.0;
        x = warpSumD(x);
        if (lane == 0) sh[0] = x;
    }
    __syncthreads();
    return sh[0];
}

// ---------------- kernel 0: init ----------------
__global__ void k_init(int B, int NMAX) {
    int i = blockIdx.x * blockDim.x + threadIdx.x;
    if (i < B * NMAX) g_key[i] = 0xFFFFFFFFull;  // iou=0, p=0 baseline
    if (i < B) { g_numpos[i] = 0; g_bdone[i] = 0; g_ldone[i] = 0; }
    if (i < 3) g_acc[i] = 0.0;
    if (i == 0) g_done = 0;
}

// ---------------- kernel 1: matching + fused override ----------------
// grid: (ceil(P/256), B) x 256; last block per batch applies overrides.
__global__ void k_match(const float* __restrict__ priors,
                        const float* __restrict__ labels,
                        const int* __restrict__ obj_count,
                        int P, int NMAX) {
    int b = blockIdx.y;
    int p = blockIdx.x * blockDim.x + threadIdx.x;

    __shared__ float4 sh_box[MAXN];
    __shared__ float  sh_area[MAXN];
    __shared__ unsigned long long sh_key[MAXN];
    __shared__ unsigned int sh_best[MAXN];
    __shared__ int s_last;

    int nv = obj_count[b];
    if (nv > NMAX) nv = NMAX;

    for (int n = threadIdx.x; n < nv; n += blockDim.x) {
        const float* g = labels + ((size_t)b * NMAX + n) * 5;
        float x0 = g[0], y0 = g[1], x1 = g[2], y1 = g[3];
        sh_box[n] = make_float4(x0, y0, x1, y1);
        sh_area[n] = (x1 - x0) * (y1 - y0);
        sh_key[n] = 0ull;
        sh_best[n] = 0u;
    }
    __syncthreads();

    if (p < P) {
        float4 pr = reinterpret_cast<const float4*>(priors)[p];
        float px0 = pr.x - 0.5f * pr.z, py0 = pr.y - 0.5f * pr.w;
        float px1 = pr.x + 0.5f * pr.z, py1 = pr.y + 0.5f * pr.w;
        float ab = pr.z * pr.w;

        float bestI = -1.0f, bestU = 1.0f;
        int bestN = 0;

        for (int n = 0; n < nv; n++) {
            float4 g = sh_box[n];
            float iw = fminf(px1, g.z) - fmaxf(px0, g.x);
            float ih = fminf(py1, g.w) - fmaxf(py0, g.y);
            if (fminf(iw, ih) > 0.0f) {
                float inter = iw * ih;
                float uni = sh_area[n] + ab - inter;
                if (inter * bestU > bestI * uni) { bestI = inter; bestU = uni; bestN = n; }
                float cur = __uint_as_float(sh_best[n]);
                if (inter > cur * uni) {
                    float iou = inter / uni;
                    unsigned int ib = __float_as_uint(iou);
                    atomicMax(&sh_best[n], ib);
                    unsigned long long key =
                        ((unsigned long long)ib << 32) |
                        (unsigned long long)(0xFFFFFFFFu - (unsigned)p);
                    atomicMax(&sh_key[n], key);
                }
            }
        }
        size_t bp = (size_t)b * P + p;
        g_bti[bp] = bestN;
        g_pos0[bp] = (bestI > 0.0f && bestI >= 0.5f * bestU) ? 1 : 0;
        g_ovr[bp] = 0;
    }
    __syncthreads();
    for (int n = threadIdx.x; n < nv; n += blockDim.x)
        if (sh_key[n]) atomicMax(&g_key[(size_t)b * NMAX + n], sh_key[n]);

    if (threadIdx.x == 0) {
        __threadfence();
        s_last = (atomicAdd(&g_bdone[b], 1) == (int)gridDim.x - 1) ? 1 : 0;
    }
    __syncthreads();
    if (s_last && threadIdx.x < nv) {
        unsigned long long key = g_key[(size_t)b * NMAX + threadIdx.x];
        unsigned int pp = 0xFFFFFFFFu - (unsigned int)(key & 0xFFFFFFFFull);
        atomicMax(&g_ovr[(size_t)b * P + pp], threadIdx.x + 1);
    }
}

// ---------------- kernel 2: per-anchor losses + fused per-batch select ----------------
// grid: (ceil(P/512), B) x 512. Last-arriving block per batch runs select.
template <int C>
__global__ void __launch_bounds__(512, 3) k_lossSel(
        const float* __restrict__ conf, const float* __restrict__ loc,
        const float* __restrict__ priors, const float* __restrict__ labels,
        float* __restrict__ out, int P, int B, int NMAX) {
    __shared__ unsigned int sv[MAXP];    // select phase only
    __shared__ int hist[2048];           // select phase only
    __shared__ int warpTot[16];
    __shared__ int s_sel;
    __shared__ double shd0[16], shd1[16];
    __shared__ int shi[16];
    __shared__ int s_last;

    int tid = threadIdx.x;
    int b = blockIdx.y;
    int p = blockIdx.x * 512 + tid;
    int lane = tid & 31, wid = tid >> 5;

    // ===== loss phase =====
    double myloc = 0.0, myce = 0.0;
    int mypos = 0;
    if (p < P) {
        size_t bp = (size_t)b * P + p;
        int ovr = g_ovr[bp];
        int n;  bool pos;
        if (ovr > 0) { n = ovr - 1; pos = true; }
        else         { n = g_bti[bp]; pos = (g_pos0[bp] != 0); }

        const float* cr = conf + bp * C;
        float r[C];
        float m = -1e30f;
#pragma unroll
        for (int c = 0; c < C; c++) { r[c] = __ldg(cr + c); m = fmaxf(m, r[c]); }
        float s = 0.0f;
#pragma unroll
        for (int c = 0; c < C; c++) s += __expf(r[c] - m);
        float lse = __logf(s) + m;

        const float* gt = labels + ((size_t)b * NMAX + n) * 5;
        int ct = pos ? ((int)__ldg(gt + 4) + 1) : 0;
        float ce = lse - r[ct];
        g_lossc[bp] = pos ? 0.0f : ce;

        if (pos) {
            mypos = 1;
            myce = (double)ce;
            float4 pr = reinterpret_cast<const float4*>(priors)[p];
            float g0 = __ldg(gt), g1 = __ldg(gt + 1), g2 = __ldg(gt + 2), g3 = __ldg(gt + 3);
            float t0 = ((g0 + g2) * 0.5f - pr.x) / (0.1f * pr.z);
            float t1 = ((g1 + g3) * 0.5f - pr.y) / (0.1f * pr.w);
            float t2 = __logf((g2 - g0) / pr.z) / 0.2f;
            float t3 = __logf((g3 - g1) / pr.w) / 0.2f;
            float4 lr = reinterpret_cast<const float4*>(loc)[bp];
            float t[4] = {t0, t1, t2, t3};
            float l[4] = {lr.x, lr.y, lr.z, lr.w};
            float acc = 0.0f;
#pragma unroll
            for (int i = 0; i < 4; i++) {
                float d = fabsf(l[i] - t[i]);
                acc += (d < 1.0f) ? 0.5f * d * d : d - 0.5f;
            }
            myloc = (double)acc;
        }
    }

    myloc = warpSumD(myloc);
    myce = warpSumD(myce);
    mypos = warpSumI(mypos);
    if (lane == 0) { shd0[wid] = myloc; shd1[wid] = myce; shi[wid] = mypos; }
    __syncthreads();
    if (tid == 0) {
        double a = 0.0, c2 = 0.0; int cp = 0;
        for (int w = 0; w < 16; w++) { a += shd0[w]; c2 += shd1[w]; cp += shi[w]; }
        if (a != 0.0) atomicAdd(&g_acc[0], a);
        if (c2 != 0.0) atomicAdd(&g_acc[1], c2);
        if (cp) atomicAdd(&g_numpos[b], cp);
    }
    __syncthreads();   // all g_lossc stores + atomics issued before counter

    if (tid == 0) {
        __threadfence();
        s_last = (atomicAdd(&g_ldone[b], 1) == (int)gridDim.x - 1) ? 1 : 0;
    }
    __syncthreads();
    if (!s_last) return;

    // ===== select phase (last block of batch b; 512 threads) =====
    __threadfence();
    {
        const float4* src = reinterpret_cast<const float4*>(g_lossc + (size_t)b * P);
        int n4 = P >> 2;
        for (int i = tid; i < n4; i += 512) {
            float4 x = src[i];
            sv[4 * i + 0] = __float_as_uint(x.x);
            sv[4 * i + 1] = __float_as_uint(x.y);
            sv[4 * i + 2] = __float_as_uint(x.z);
            sv[4 * i + 3] = __float_as_uint(x.w);
        }
        for (int i = (n4 << 2) + tid; i < P; i += 512)
            sv[i] = __float_as_uint(__ldcg(g_lossc + (size_t)b * P + i));
    }
    int npos = __ldcg(&g_numpos[b]);
    int k = 3 * npos;
    if (k > P - 1) k = P - 1;
    __syncthreads();

    if (k > 0) {
        unsigned int prefix = 0;
        int kk = k;
        int iters = (P + 511) / 512;

        for (int r = 0; r < 2; r++) {
            int shift = r ? 10 : 21;
            // zero hist
            hist[tid] = 0; hist[tid + 512] = 0; hist[tid + 1024] = 0; hist[tid + 1536] = 0;
            if (tid == 0) s_sel = 0;
            __syncthreads();

            // warp-aggregated histogram
            for (int j = 0; j < iters; j++) {
                int i = tid + j * 512;
                bool valid = (i < P);
                unsigned int v = valid ? sv[i] : 0u;
                if (r) valid = valid && ((v >> 21) == prefix);
                unsigned int bm = __ballot_sync(0xFFFFFFFFu, valid);
                if (valid) {
                    int bin = (v >> shift) & 2047;
                    unsigned int mm = __match_any_sync(bm, bin);
                    if (lane == __ffs(mm) - 1) atomicAdd(&hist[bin], __popc(mm));
                }
            }
            __syncthreads();

            // suffix scan: 4 consecutive bins per thread
            int h0 = hist[4 * tid], h1 = hist[4 * tid + 1];
            int h2 = hist[4 * tid + 2], h3 = hist[4 * tid + 3];
            int v4 = h0 + h1 + h2 + h3;
            int sIncl = warpSufI(v4);
            if (lane == 0) warpTot[wid] = sIncl;
            __syncthreads();
            if (wid == 0) {
                int t = (lane < 16) ? warpTot[lane] : 0;
                int ws = warpSufI(t);
                if (lane < 16) warpTot[lane] = ws - t;   // warps > wid
            }
            __syncthreads();
            int E = (sIncl - v4) + warpTot[wid];        // threads > tid
            int s3 = E + h3, s2 = s3 + h2, s1_ = s2 + h1, s0 = s1_ + h0;
            hist[4 * tid] = s0; hist[4 * tid + 1] = s1_;
            hist[4 * tid + 2] = s2; hist[4 * tid + 3] = s3;
            int cand = -1;
            if (s3 >= kk) cand = 4 * tid + 3;
            else if (s2 >= kk) cand = 4 * tid + 2;
            else if (s1_ >= kk) cand = 4 * tid + 1;
            else if (s0 >= kk) cand = 4 * tid;
            if (cand >= 0) atomicMax(&s_sel, cand);
            __syncthreads();
            int d = s_sel;
            int above = (d + 1 < 2048) ? hist[d + 1] : 0;
            kk -= above;
            prefix = (prefix << 11) | (unsigned int)d;
            __syncthreads();
        }

        unsigned int T = prefix << 10;   // exact to 22 bits
        int c1 = 0;
        double ssum = 0.0;
        for (int i = tid; i < P; i += 512) {
            unsigned int v = sv[i];
            if (v > T) { c1++; ssum += (double)__uint_as_float(v); }
        }
        c1 = blockSumI(c1, shi);
        ssum = blockSumD(ssum, shd0);
        if (tid == 0)
            atomicAdd(&g_acc[2], ssum + (double)(k - c1) * (double)__uint_as_float(T));
    }

    // elected finalize across the B select blocks
    if (tid == 0) {
        __threadfence();
        if (atomicAdd(&g_done, 1) == B - 1) {
            long long N = 0;
            for (int bb = 0; bb < B; bb++) N += __ldcg(&g_numpos[bb]);
            double Nd = (double)N;
            double a0 = __ldcg(&g_acc[0]);
            double a1 = __ldcg(&g_acc[1]);
            double a2 = __ldcg(&g_acc[2]);
            out[0] = (float)(a0 / Nd);
            out[1] = (float)((a1 + a2) / Nd);
        }
    }
}

// ---------------- launch ----------------
extern "C" void kernel_launch(void* const* d_in, const int* in_sizes, int n_in,
                              void* d_out, int out_size) {
    const float* conf   = (const float*)d_in[0];
    const float* loc    = (const float*)d_in[1];
    const float* priors = (const float*)d_in[2];
    const float* labels = (const float*)d_in[3];
    const int*   obj    = (const int*)d_in[4];

    int P = in_sizes[2] / 4;
    int B = in_sizes[4];
    int NMAX = in_sizes[3] / (B * 5);

    k_init<<<(B * NMAX + 1023) / 1024, 1024>>>(B, NMAX);

    dim3 gm((P + 255) / 256, B);
    k_match<<<gm, 256>>>(priors, labels, obj, P, NMAX);

    dim3 gl((P + 511) / 512, B);
    k_lossSel<21><<<gl, 512>>>(conf, loc, priors, labels, (float*)d_out, P, B, NMAX);
}

// round 7
// speedup vs baseline: 1.1312x; 1.1312x over previous
#include <cuda_runtime.h>
#include <cstdint>

#define MAXB 64
#define MAXP 8800
#define MAXN 64

// ---------------- scratch (device globals; zero-init at load, self-restoring) ----
__device__ int                g_bti[MAXB * MAXP];     // best_truth_idx
__device__ int                g_pos0[MAXB * MAXP];    // iou >= 0.5 flag
__device__ int                g_ovr[MAXB * MAXP];     // override: n+1, 0 = none
__device__ float              g_lossc[MAXB * MAXP];   // loss_c (0 for pos)
__device__ unsigned long long g_key[MAXB * MAXN];     // per-GT best prior key (0 = none)
__device__ int                g_numpos[MAXB];
__device__ int                g_bdone[MAXB];          // match completion per batch
__device__ int                g_done;                 // select completion
__device__ double             g_acc[3];               // loc, ce_pos, ce_neg

// ---------------- reductions ----------------
__device__ __forceinline__ double warpSumD(double v) {
#pragma unroll
    for (int o = 16; o; o >>= 1) v += __shfl_down_sync(0xFFFFFFFFu, v, o);
    return v;
}
__device__ __forceinline__ int warpSumI(int v) {
#pragma unroll
    for (int o = 16; o; o >>= 1) v += __shfl_down_sync(0xFFFFFFFFu, v, o);
    return v;
}
// inclusive suffix sum within warp: result(lane) = sum over lanes >= lane
__device__ __forceinline__ int warpSufI(int v) {
    int lane = threadIdx.x & 31;
#pragma unroll
    for (int o = 1; o < 32; o <<= 1) {
        int t = __shfl_down_sync(0xFFFFFFFFu, v, o);
        if (lane + o < 32) v += t;
    }
    return v;
}

__device__ int blockSumI(int v, int* sh) {
    __syncthreads();
    int lane = threadIdx.x & 31, wid = threadIdx.x >> 5;
    v = warpSumI(v);
    if (lane == 0) sh[wid] = v;
    __syncthreads();
    if (wid == 0) {
        int nw = (blockDim.x + 31) >> 5;
        int x = (lane < nw) ? sh[lane] : 0;
        x = warpSumI(x);
        if (lane == 0) sh[0] = x;
    }
    __syncthreads();
    return sh[0];
}

__device__ double blockSumD(double v, double* sh) {
    __syncthreads();
    int lane = threadIdx.x & 31, wid = threadIdx.x >> 5;
    v = warpSumD(v);
    if (lane == 0) sh[wid] = v;
    __syncthreads();
    if (wid == 0) {
        int nw = (blockDim.x + 31) >> 5;
        double x = (lane < nw) ? sh[lane] : 0.0;
        x = warpSumD(x);
        if (lane == 0) sh[0] = x;
    }
    __syncthreads();
    return sh[0];
}

// ---------------- kernel 1: matching (2 threads per prior) + fused override ----
// grid: (ceil(P/128), B) x 256. Thread pair (2t, 2t+1) splits the GT list.
__global__ void __launch_bounds__(256) k_match(
        const float* __restrict__ priors, const float* __restrict__ labels,
        const int* __restrict__ obj_count, int P, int NMAX) {
    int b = blockIdx.y;
    int tid = threadIdx.x;
    int idx = tid >> 1;          // prior slot 0..127
    int sub = tid & 1;           // GT-half
    int p = blockIdx.x * 128 + idx;
    bool valid = (p < P);
    int pl = valid ? p : (P - 1);

    __shared__ float4 sh_box[MAXN];
    __shared__ float  sh_area[MAXN];
    __shared__ unsigned long long sh_key[MAXN];
    __shared__ unsigned int sh_best[MAXN];
    __shared__ int s_last;

    int nv = obj_count[b];
    if (nv > NMAX) nv = NMAX;

    for (int n = tid; n < nv; n += 256) {
        const float* g = labels + ((size_t)b * NMAX + n) * 5;
        float x0 = g[0], y0 = g[1], x1 = g[2], y1 = g[3];
        sh_box[n] = make_float4(x0, y0, x1, y1);
        sh_area[n] = (x1 - x0) * (y1 - y0);
        sh_key[n] = 0ull;
        sh_best[n] = 0u;
    }
    __syncthreads();

    float4 pr = reinterpret_cast<const float4*>(priors)[pl];
    float px0 = pr.x - 0.5f * pr.z, py0 = pr.y - 0.5f * pr.w;
    float px1 = pr.x + 0.5f * pr.z, py1 = pr.y + 0.5f * pr.w;
    float ab = pr.z * pr.w;

    int nv2 = nv >> 1;
    int nlo = sub ? nv2 : 0;
    int nhi = sub ? nv : nv2;

    float bestI = -1.0f, bestU = 1.0f;
    int bestN = 0;

    for (int n = nlo; n < nhi; n++) {
        float4 g = sh_box[n];
        float iw = fminf(px1, g.z) - fmaxf(px0, g.x);
        float ih = fminf(py1, g.w) - fmaxf(py0, g.y);
        if (fminf(iw, ih) > 0.0f) {
            float inter = iw * ih;
            float uni = sh_area[n] + ab - inter;
            if (inter * bestU > bestI * uni) { bestI = inter; bestU = uni; bestN = n; }
            if (valid) {
                float cur = __uint_as_float(sh_best[n]);
                if (inter > cur * uni) {
                    float iou = inter / uni;
                    unsigned int ib = __float_as_uint(iou);
                    atomicMax(&sh_best[n], ib);
                    unsigned long long key =
                        ((unsigned long long)ib << 32) |
                        (unsigned long long)(0xFFFFFFFFu - (unsigned)p);
                    atomicMax(&sh_key[n], key);
                }
            }
        }
    }

    // merge the pair (xor 1): strictly greater wins; exact tie -> lower n
    {
        float oI = __shfl_xor_sync(0xFFFFFFFFu, bestI, 1);
        float oU = __shfl_xor_sync(0xFFFFFFFFu, bestU, 1);
        int   oN = __shfl_xor_sync(0xFFFFFFFFu, bestN, 1);
        float a = oI * bestU, c = bestI * oU;
        if (a > c || (a == c && oN < bestN)) { bestI = oI; bestU = oU; bestN = oN; }
    }

    if (valid && sub == 0) {
        size_t bp = (size_t)b * P + p;
        g_bti[bp] = bestN;
        g_pos0[bp] = (bestI > 0.0f && bestI >= 0.5f * bestU) ? 1 : 0;
        g_ovr[bp] = 0;
    }
    __syncthreads();
    for (int n = tid; n < nv; n += 256)
        if (sh_key[n]) atomicMax(&g_key[(size_t)b * NMAX + n], sh_key[n]);

    // elect last block of this batch: apply overrides, then restore state
    if (tid == 0) {
        __threadfence();
        s_last = (atomicAdd(&g_bdone[b], 1) == (int)gridDim.x - 1) ? 1 : 0;
    }
    __syncthreads();
    if (s_last) {
        if (tid < nv) {
            unsigned long long key = g_key[(size_t)b * NMAX + tid];
            // key == 0 means no intersecting prior -> argmax over zeros = 0
            unsigned int pp = key ? (0xFFFFFFFFu - (unsigned int)(key & 0xFFFFFFFFull)) : 0u;
            atomicMax(&g_ovr[(size_t)b * P + pp], tid + 1);
            g_key[(size_t)b * NMAX + tid] = 0ull;   // restore for next replay
        }
        if (tid == 0) g_bdone[b] = 0;               // restore counter
    }
}

// ---------------- kernel 2: per-anchor losses (smem-staged, 2 anchors/thread) ----
// grid: (ceil(P/256), B) x 128
template <int C>
__global__ void __launch_bounds__(128) k_loss(
        const float* __restrict__ conf, const float* __restrict__ loc,
        const float* __restrict__ priors, const float* __restrict__ labels,
        int P, int NMAX) {
    __shared__ float4 shc4[(256 * C + 8) / 4];
    __shared__ float4 sh_box[MAXN];
    __shared__ float  sh_cls[MAXN];
    float* shc = (float*)shc4;

    int tid = threadIdx.x;
    int b = blockIdx.y;
    int p0 = blockIdx.x * 256;
    int cnt = min(256, P - p0);

    // stage conf tile (coalesced float4 from 16B-aligned-down start)
    size_t base_byte = ((size_t)b * P + p0) * C * 4;
    size_t gstart = base_byte & ~(size_t)15;
    int lead = (int)((base_byte - gstart) >> 2);
    int nfl = lead + cnt * C;
    int nf4 = nfl >> 2, rem = nfl & 3;
    const float4* s4 = reinterpret_cast<const float4*>((const char*)conf + gstart);
    for (int i = tid; i < nf4; i += 128) shc4[i] = s4[i];
    if (tid < rem) shc[nf4 * 4 + tid] = ((const float*)s4)[nf4 * 4 + tid];

    for (int n = tid; n < NMAX; n += 128) {
        const float* g = labels + ((size_t)b * NMAX + n) * 5;
        sh_box[n] = make_float4(g[0], g[1], g[2], g[3]);
        sh_cls[n] = g[4];
    }
    __syncthreads();

    double myloc = 0.0, myce = 0.0;
    int mypos = 0;

#pragma unroll
    for (int half = 0; half < 2; half++) {
        int row = tid + half * 128;
        int p = p0 + row;
        if (p >= P) break;
        size_t bp = (size_t)b * P + p;

        int ovr = g_ovr[bp];
        int n;  bool pos;
        if (ovr > 0) { n = ovr - 1; pos = true; }
        else         { n = g_bti[bp]; pos = (g_pos0[bp] != 0); }
        int ct = pos ? ((int)sh_cls[n] + 1) : 0;

        const float* vv = shc + lead + row * C;
        float m = vv[0];
#pragma unroll
        for (int c = 1; c < C; c++) m = fmaxf(m, vv[c]);
        float s = 0.0f;
#pragma unroll
        for (int c = 0; c < C; c++) s += __expf(vv[c] - m);
        float ce = __logf(s) + m - vv[ct];
        g_lossc[bp] = pos ? 0.0f : ce;

        if (pos) {
            mypos++;
            myce += (double)ce;
            float4 pr = reinterpret_cast<const float4*>(priors)[p];
            float4 g = sh_box[n];
            float t0 = ((g.x + g.z) * 0.5f - pr.x) / (0.1f * pr.z);
            float t1 = ((g.y + g.w) * 0.5f - pr.y) / (0.1f * pr.w);
            float t2 = __logf((g.z - g.x) / pr.z) / 0.2f;
            float t3 = __logf((g.w - g.y) / pr.w) / 0.2f;
            float4 lr = reinterpret_cast<const float4*>(loc)[bp];
            float t[4] = {t0, t1, t2, t3};
            float l[4] = {lr.x, lr.y, lr.z, lr.w};
            float acc = 0.0f;
#pragma unroll
            for (int i = 0; i < 4; i++) {
                float d = fabsf(l[i] - t[i]);
                acc += (d < 1.0f) ? 0.5f * d * d : d - 0.5f;
            }
            myloc += (double)acc;
        }
    }

    __shared__ double shd0[4], shd1[4];
    __shared__ int shi[4];
    int lane = tid & 31, wid = tid >> 5;
    myloc = warpSumD(myloc);
    myce = warpSumD(myce);
    mypos = warpSumI(mypos);
    if (lane == 0) { shd0[wid] = myloc; shd1[wid] = myce; shi[wid] = mypos; }
    __syncthreads();
    if (tid == 0) {
        double a = 0.0, c2 = 0.0; int cp = 0;
        for (int w = 0; w < 4; w++) { a += shd0[w]; c2 += shd1[w]; cp += shi[w]; }
        if (a != 0.0) atomicAdd(&g_acc[0], a);
        if (c2 != 0.0) atomicAdd(&g_acc[1], c2);
        if (cp) atomicAdd(&g_numpos[b], cp);
    }
}

// ---------------- kernel 3: 2-round radix top-k selection + finalize + restore ----
// grid: B blocks x 1024
__global__ void k_select(float* __restrict__ out, int P, int B) {
    int b = blockIdx.x;
    __shared__ unsigned int sv[MAXP];
    __shared__ int hist[2048];
    __shared__ int warpTot[32];
    __shared__ int s_ri[32];
    __shared__ double s_rd[32];
    __shared__ int s_sel;
    int tid = threadIdx.x, nt = blockDim.x;
    int lane = tid & 31, wid = tid >> 5;

    for (int i = tid; i < P; i += nt)
        sv[i] = __float_as_uint(g_lossc[(size_t)b * P + i]);

    int npos = g_numpos[b];
    int k = 3 * npos;
    if (k > P - 1) k = P - 1;
    __syncthreads();

    if (k > 0) {
        unsigned int prefix = 0;
        int kk = k;
        int iters = (P + nt - 1) / nt;

        for (int r = 0; r < 2; r++) {
            int shift = r ? 10 : 21;
            hist[tid] = 0; hist[tid + 1024] = 0;
            if (tid == 0) s_sel = 0;
            __syncthreads();

            for (int j = 0; j < iters; j++) {
                int i = tid + j * nt;
                bool val = (i < P);
                unsigned int v = val ? sv[i] : 0u;
                if (r) val = val && ((v >> 21) == prefix);
                unsigned int bm = __ballot_sync(0xFFFFFFFFu, val);
                if (val) {
                    int bin = (v >> shift) & 2047;
                    unsigned int mm = __match_any_sync(bm, bin);
                    if (lane == __ffs(mm) - 1) atomicAdd(&hist[bin], __popc(mm));
                }
            }
            __syncthreads();

            // suffix scan: 2 consecutive bins per thread
            int h0 = hist[2 * tid], h1 = hist[2 * tid + 1];
            int v2 = h0 + h1;
            int sIncl = warpSufI(v2);
            if (lane == 0) warpTot[wid] = sIncl;
            __syncthreads();
            if (wid == 0) {
                int t = warpTot[lane];
                int ws = warpSufI(t);
                warpTot[lane] = ws - t;
            }
            __syncthreads();
            int E = (sIncl - v2) + warpTot[wid];
            int suf1 = E + h1, suf0 = suf1 + h0;
            hist[2 * tid] = suf0; hist[2 * tid + 1] = suf1;
            int cand = -1;
            if (suf1 >= kk) cand = 2 * tid + 1;
            else if (suf0 >= kk) cand = 2 * tid;
            if (cand >= 0) atomicMax(&s_sel, cand);
            __syncthreads();
            int d = s_sel;
            int above = (d + 1 < 2048) ? hist[d + 1] : 0;
            kk -= above;
            prefix = (prefix << 11) | (unsigned int)d;
            __syncthreads();
        }

        unsigned int T = prefix << 10;   // threshold exact to 22 bits (validated)
        int c1 = 0;
        double ssum = 0.0;
        for (int i = tid; i < P; i += nt) {
            unsigned int v = sv[i];
            if (v > T) { c1++; ssum += (double)__uint_as_float(v); }
        }
        c1 = blockSumI(c1, s_ri);
        ssum = blockSumD(ssum, s_rd);
        if (tid == 0)
            atomicAdd(&g_acc[2], ssum + (double)(k - c1) * (double)__uint_as_float(T));
    }

    // elected finalize + state restore
    if (tid == 0) {
        __threadfence();
        if (atomicAdd(&g_done, 1) == (int)gridDim.x - 1) {
            long long N = 0;
            for (int bb = 0; bb < B; bb++) N += __ldcg(&g_numpos[bb]);
            double Nd = (double)N;
            double a0 = __ldcg(&g_acc[0]);
            double a1 = __ldcg(&g_acc[1]);
            double a2 = __ldcg(&g_acc[2]);
            out[0] = (float)(a0 / Nd);
            out[1] = (float)((a1 + a2) / Nd);
            // restore for next graph replay
            for (int bb = 0; bb < B; bb++) g_numpos[bb] = 0;
            g_acc[0] = 0.0; g_acc[1] = 0.0; g_acc[2] = 0.0;
            g_done = 0;
        }
    }
}

// ---------------- launch ----------------
extern "C" void kernel_launch(void* const* d_in, const int* in_sizes, int n_in,
                              void* d_out, int out_size) {
    const float* conf   = (const float*)d_in[0];
    const float* loc    = (const float*)d_in[1];
    const float* priors = (const float*)d_in[2];
    const float* labels = (const float*)d_in[3];
    const int*   obj    = (const int*)d_in[4];

    int P = in_sizes[2] / 4;
    int B = in_sizes[4];
    int NMAX = in_sizes[3] / (B * 5);

    dim3 gm((P + 127) / 128, B);
    k_match<<<gm, 256>>>(priors, labels, obj, P, NMAX);

    dim3 gl((P + 255) / 256, B);
    k_loss<21><<<gl, 128>>>(conf, loc, priors, labels, P, NMAX);

    k_select<<<B, 1024>>>((float*)d_out, P, B);
}